// round 6
// baseline (speedup 1.0000x reference)
#include <cuda_runtime.h>
#include <cstdint>

#define NN 50000
#define NE 320000
#define HID 256
#define NLAYERS 5
#define BN_EPS 1e-5f
#define NB_SCAN ((NN + 255) / 256)   // 196

// ---------------- scratch (device globals; no allocation allowed) -------------
__device__ float g_h[(size_t)NN * HID];     // h after BN (layer output)
__device__ float g_agg[(size_t)NN * HID];   // aggregation result
__device__ float g_tmp[(size_t)NN * HID];   // pre-BN activations
__device__ float g_dinv[NN];
__device__ int   g_degi[NN];
__device__ int   g_off[NN + 1];
__device__ int   g_cur[NN];
__device__ int   g_row[NE];    // CSR-ordered source node per slot
__device__ float g_nrm[NE];    // CSR-ordered norm per slot
__device__ float g_S[(size_t)NN * 4];  // per-node sum norm*ea (layer-invariant)
__device__ float g_cs[HID];
__device__ float g_cs2[HID];
__device__ int   g_part[256];
__device__ int   g_is64;       // 1 if edge_index buffer is int64, 0 if int32

// ---------------- edge-index dtype detection ----------------------------------
__global__ void detect_kernel(const int* __restrict__ ei32) {
    __shared__ int nz;
    if (threadIdx.x == 0) nz = 0;
    __syncthreads();
    int cnt = 0;
    for (int i = threadIdx.x; i < 4096; i += blockDim.x)
        if (ei32[2 * i + 1] != 0) cnt++;
    atomicAdd(&nz, cnt);
    __syncthreads();
    if (threadIdx.x == 0) g_is64 = (nz == 0) ? 1 : 0;
}

__device__ __forceinline__ int fetch_idx(const void* ei, int part, int e) {
    int v;
    if (g_is64) v = (int)((const long long*)ei)[(size_t)part * NE + e];
    else        v = ((const int*)ei)[(size_t)part * NE + e];
    return (v < 0 || v >= NN) ? 0 : v;
}

// ---------------- CSR build ---------------------------------------------------
__global__ void zero_init_kernel() {
    int i = blockIdx.x * blockDim.x + threadIdx.x;
    if (i < NN) { g_degi[i] = 0; g_cur[i] = 0; }
    if (i < NN * 4) g_S[i] = 0.0f;
}

__global__ void count_kernel(const void* __restrict__ ei) {
    int e = blockIdx.x * blockDim.x + threadIdx.x;
    if (e < NE) atomicAdd(&g_degi[fetch_idx(ei, 1, e)], 1);
}

// 3-phase multi-block exclusive scan of g_degi -> g_off  (+ fused dinv)
__global__ void scan1_kernel() {
    __shared__ int sh[256];
    int i = blockIdx.x * 256 + threadIdx.x;
    int v = (i < NN) ? g_degi[i] : 0;
    sh[threadIdx.x] = v;
    __syncthreads();
    for (int s = 128; s > 0; s >>= 1) {
        if (threadIdx.x < s) sh[threadIdx.x] += sh[threadIdx.x + s];
        __syncthreads();
    }
    if (threadIdx.x == 0) g_part[blockIdx.x] = sh[0];
}

__global__ void scan2_kernel() {
    __shared__ int sh[256];
    int t = threadIdx.x;
    sh[t] = (t < NB_SCAN) ? g_part[t] : 0;
    __syncthreads();
    for (int off = 1; off < 256; off <<= 1) {
        int v = (t >= off) ? sh[t - off] : 0;
        __syncthreads();
        sh[t] += v;
        __syncthreads();
    }
    g_part[t] = (t == 0) ? 0 : sh[t - 1];
}

__global__ void scan3_kernel() {
    __shared__ int sh[256];
    int t = threadIdx.x;
    int i = blockIdx.x * 256 + t;
    int v = (i < NN) ? g_degi[i] : 0;
    sh[t] = v;
    __syncthreads();
    for (int off = 1; off < 256; off <<= 1) {
        int x = (t >= off) ? sh[t - off] : 0;
        __syncthreads();
        sh[t] += x;
        __syncthreads();
    }
    int excl = sh[t] - v + g_part[blockIdx.x];
    if (i < NN) {
        g_off[i] = excl;
        g_dinv[i] = (v > 0) ? rsqrtf((float)v) : 0.0f;
        if (i == NN - 1) g_off[NN] = excl + v;
    }
}

__global__ void fill_kernel(const void* __restrict__ ei) {
    int e = blockIdx.x * blockDim.x + threadIdx.x;
    if (e < NE) {
        int r = fetch_idx(ei, 0, e);
        int c = fetch_idx(ei, 1, e);
        int p = atomicAdd(&g_cur[c], 1);
        int slot = g_off[c] + p;
        if (slot >= 0 && slot < NE) {
            g_row[slot] = r;
            g_nrm[slot] = g_dinv[r] * g_dinv[c];
        }
    }
}

__global__ void sedge_kernel(const void* __restrict__ ei,
                             const float* __restrict__ ea) {
    int e = blockIdx.x * blockDim.x + threadIdx.x;
    if (e < NE) {
        int r = fetch_idx(ei, 0, e);
        int c = fetch_idx(ei, 1, e);
        float nrm = g_dinv[r] * g_dinv[c];
        float4 v = *(const float4*)(ea + (size_t)e * 4);
        float* s = g_S + (size_t)c * 4;
        atomicAdd(s + 0, nrm * v.x);
        atomicAdd(s + 1, nrm * v.y);
        atomicAdd(s + 2, nrm * v.z);
        atomicAdd(s + 3, nrm * v.w);
    }
}

// ---------------- aggregation: one warp per destination node ------------------
__global__ void __launch_bounds__(256) agg_kernel(
    const float* __restrict__ x_ext, int use_ext,
    const float* __restrict__ ew1, const float* __restrict__ ew2)
{
    int warp = (blockIdx.x * blockDim.x + threadIdx.x) >> 5;
    int ln = threadIdx.x & 31;
    if (warp >= NN) return;

    const float* hin = use_ext ? x_ext : g_h;

    float acc[8];
#pragma unroll
    for (int k = 0; k < 8; k++) acc[k] = 0.0f;

    int s = g_off[warp];
    int e_end = g_off[warp + 1];
    for (int i = s; i < e_end; i++) {
        int r = g_row[i];
        float nrm = g_nrm[i];
        const float* hr = hin + (size_t)r * HID;
#pragma unroll
        for (int k = 0; k < 8; k++)
            acc[k] = fmaf(nrm, __ldg(hr + ln + 32 * k), acc[k]);
    }

    float4 S = *(const float4*)(g_S + (size_t)warp * 4);
    float* o = g_agg + (size_t)warp * HID;
#pragma unroll
    for (int k = 0; k < 8; k++) {
        int j = ln + 32 * k;
        float fea;
        if (k < 4) {
            fea = S.w * ew1[j];
        } else {
            int jj = j - 128;
            fea = fmaf(S.x, ew2[jj], fmaf(S.y, ew2[128 + jj], S.z * ew2[256 + jj]));
        }
        o[j] = acc[k] + fea;
    }
}

// ---------------- tensor-core GEMM (3xTF32 mma.sync, fp32-accurate) -----------
// g_tmp = relu([hin, g_agg] @ W + b);  W [512,256] row-major.
__device__ __forceinline__ uint32_t f2tf32(float f) {
    uint32_t r;
    asm("cvt.rna.tf32.f32 %0, %1;" : "=r"(r) : "f"(f));
    return r;
}

#define PADA 20   // k-chunk 16 + 4 pad
#define PADB 132  // n 128 + 4 pad

__global__ void __launch_bounds__(256) gemm_tc_kernel(
    const float* __restrict__ x_ext, int use_ext,
    const float* __restrict__ W, const float* __restrict__ bias)
{
    __shared__ uint32_t AsH[128][PADA], AsL[128][PADA];
    __shared__ uint32_t BsH[16][PADB],  BsL[16][PADB];

    const float* A1 = use_ext ? x_ext : g_h;
    int tid = threadIdx.x;
    int wid = tid >> 5, lane = tid & 31;
    int gid = lane >> 2, tig = lane & 3;
    int warp_m = wid >> 2;               // 0..1 -> 64 rows each
    int warp_n = wid & 3;                // 0..3 -> 32 cols each
    int rowBase = blockIdx.y * 128;
    int colBase = blockIdx.x * 128;

    float c[4][4][4];
#pragma unroll
    for (int mi = 0; mi < 4; mi++)
#pragma unroll
        for (int ni = 0; ni < 4; ni++)
#pragma unroll
            for (int q = 0; q < 4; q++) c[mi][ni][q] = 0.0f;

    for (int k0 = 0; k0 < 512; k0 += 16) {
        const float* A = (k0 < 256) ? A1 : (const float*)g_agg;
        const float* Wp = W + ((k0 < 256) ? 0 : (size_t)256 * 256);
        int ka = k0 & 255;

        // stage A: 128x16 (each thread: 2 float4)
#pragma unroll
        for (int it = 0; it < 2; it++) {
            int m = it * 64 + (tid >> 2);
            int kk = (tid & 3) * 4;
            int r = rowBase + m;
            float4 v = make_float4(0.f, 0.f, 0.f, 0.f);
            if (r < NN) v = *(const float4*)(A + (size_t)r * 256 + ka + kk);
            float f[4] = {v.x, v.y, v.z, v.w};
#pragma unroll
            for (int q = 0; q < 4; q++) {
                uint32_t hi = f2tf32(f[q]);
                AsH[m][kk + q] = hi;
                AsL[m][kk + q] = f2tf32(f[q] - __uint_as_float(hi));
            }
        }
        // stage B: 16x128 (each thread: 2 float4)
#pragma unroll
        for (int it = 0; it < 2; it++) {
            int kk = it * 8 + (tid >> 5);
            int n = lane * 4;
            float4 v = *(const float4*)(Wp + (size_t)(ka + kk) * 256 + colBase + n);
            float f[4] = {v.x, v.y, v.z, v.w};
#pragma unroll
            for (int q = 0; q < 4; q++) {
                uint32_t hi = f2tf32(f[q]);
                BsH[kk][n + q] = hi;
                BsL[kk][n + q] = f2tf32(f[q] - __uint_as_float(hi));
            }
        }
        __syncthreads();

#pragma unroll
        for (int ks = 0; ks < 2; ks++) {
            int kb = ks * 8;
            uint32_t aH[4][4], aL[4][4], bH[4][2], bL[4][2];
#pragma unroll
            for (int mi = 0; mi < 4; mi++) {
                int m0 = warp_m * 64 + mi * 16;
                aH[mi][0] = AsH[m0 + gid][kb + tig];
                aH[mi][1] = AsH[m0 + gid + 8][kb + tig];
                aH[mi][2] = AsH[m0 + gid][kb + tig + 4];
                aH[mi][3] = AsH[m0 + gid + 8][kb + tig + 4];
                aL[mi][0] = AsL[m0 + gid][kb + tig];
                aL[mi][1] = AsL[m0 + gid + 8][kb + tig];
                aL[mi][2] = AsL[m0 + gid][kb + tig + 4];
                aL[mi][3] = AsL[m0 + gid + 8][kb + tig + 4];
            }
#pragma unroll
            for (int ni = 0; ni < 4; ni++) {
                int n0 = warp_n * 32 + ni * 8;
                bH[ni][0] = BsH[kb + tig][n0 + gid];
                bH[ni][1] = BsH[kb + tig + 4][n0 + gid];
                bL[ni][0] = BsL[kb + tig][n0 + gid];
                bL[ni][1] = BsL[kb + tig + 4][n0 + gid];
            }
#define MMA(cc, av, bv)                                                        \
    asm volatile(                                                              \
        "mma.sync.aligned.m16n8k8.row.col.f32.tf32.tf32.f32 "                  \
        "{%0,%1,%2,%3}, {%4,%5,%6,%7}, {%8,%9}, {%0,%1,%2,%3};"                \
        : "+f"(cc[0]), "+f"(cc[1]), "+f"(cc[2]), "+f"(cc[3])                   \
        : "r"(av[0]), "r"(av[1]), "r"(av[2]), "r"(av[3]),                      \
          "r"(bv[0]), "r"(bv[1]))
#pragma unroll
            for (int mi = 0; mi < 4; mi++)
#pragma unroll
                for (int ni = 0; ni < 4; ni++) {
                    MMA(c[mi][ni], aL[mi], bH[ni]);   // lo*hi
                    MMA(c[mi][ni], aH[mi], bL[ni]);   // hi*lo
                    MMA(c[mi][ni], aH[mi], bH[ni]);   // hi*hi (last: largest term)
                }
#undef MMA
        }
        __syncthreads();
    }

    // epilogue: bias + relu -> g_tmp
#pragma unroll
    for (int mi = 0; mi < 4; mi++) {
        int r0 = rowBase + warp_m * 64 + mi * 16 + gid;
        int r1 = r0 + 8;
#pragma unroll
        for (int ni = 0; ni < 4; ni++) {
            int col = colBase + warp_n * 32 + ni * 8 + tig * 2;
            float b0 = bias[col], b1 = bias[col + 1];
            if (r0 < NN) {
                float2 v;
                v.x = fmaxf(c[mi][ni][0] + b0, 0.0f);
                v.y = fmaxf(c[mi][ni][1] + b1, 0.0f);
                *(float2*)(g_tmp + (size_t)r0 * 256 + col) = v;
            }
            if (r1 < NN) {
                float2 v;
                v.x = fmaxf(c[mi][ni][2] + b0, 0.0f);
                v.y = fmaxf(c[mi][ni][3] + b1, 0.0f);
                *(float2*)(g_tmp + (size_t)r1 * 256 + col) = v;
            }
        }
    }
}

// ---------------- BatchNorm ---------------------------------------------------
__global__ void zero_stats_kernel() {
    int t = threadIdx.x;
    if (t < HID) g_cs[t] = 0.0f;
    else if (t < 2 * HID) g_cs2[t - HID] = 0.0f;
}

__global__ void __launch_bounds__(256) bnstat_kernel() {
    int c = threadIdx.x;
    int r0 = blockIdx.x * 128;
    int r1 = min(r0 + 128, NN);
    float s = 0.0f, s2 = 0.0f;
    for (int r = r0; r < r1; r++) {
        float v = g_tmp[(size_t)r * HID + c];
        s += v;
        s2 += v * v;
    }
    atomicAdd(&g_cs[c], s);
    atomicAdd(&g_cs2[c], s2);
}

__global__ void __launch_bounds__(256) bnapply_kernel(
    float* __restrict__ out_ext, int use_ext,
    const float* __restrict__ gamma, const float* __restrict__ beta, int dorelu)
{
    int idx = blockIdx.x * blockDim.x + threadIdx.x;   // over NN*HID/4
    if (idx >= NN * HID / 4) return;
    float* O = use_ext ? out_ext : g_h;
    int c4 = idx & 63;
    const float invn = 1.0f / (float)NN;
    float4 cs  = ((const float4*)g_cs)[c4];
    float4 cs2 = ((const float4*)g_cs2)[c4];
    float4 gm  = ((const float4*)gamma)[c4];
    float4 bt  = ((const float4*)beta)[c4];
    float4 xv  = ((const float4*)g_tmp)[idx];
    float4 ov;
    {
        float mu = cs.x * invn, var = cs2.x * invn - mu * mu;
        ov.x = (xv.x - mu) * rsqrtf(var + BN_EPS) * gm.x + bt.x;
        mu = cs.y * invn; var = cs2.y * invn - mu * mu;
        ov.y = (xv.y - mu) * rsqrtf(var + BN_EPS) * gm.y + bt.y;
        mu = cs.z * invn; var = cs2.z * invn - mu * mu;
        ov.z = (xv.z - mu) * rsqrtf(var + BN_EPS) * gm.z + bt.z;
        mu = cs.w * invn; var = cs2.w * invn - mu * mu;
        ov.w = (xv.w - mu) * rsqrtf(var + BN_EPS) * gm.w + bt.w;
    }
    if (dorelu) {
        ov.x = fmaxf(ov.x, 0.0f); ov.y = fmaxf(ov.y, 0.0f);
        ov.z = fmaxf(ov.z, 0.0f); ov.w = fmaxf(ov.w, 0.0f);
    }
    ((float4*)O)[idx] = ov;
}

// ---------------- launch ------------------------------------------------------
extern "C" void kernel_launch(void* const* d_in, const int* in_sizes, int n_in,
                              void* d_out, int out_size) {
    const float* x     = (const float*)d_in[0];
    const void*  ei    = d_in[1];
    const float* ea    = (const float*)d_in[2];
    const float* mlp_w = (const float*)d_in[3];
    const float* mlp_b = (const float*)d_in[4];
    const float* ew1   = (const float*)d_in[5];
    const float* ew2   = (const float*)d_in[6];
    const float* bn_g  = (const float*)d_in[7];
    const float* bn_b  = (const float*)d_in[8];
    float* out = (float*)d_out;

    detect_kernel<<<1, 256>>>((const int*)ei);
    zero_init_kernel<<<(NN * 4 + 255) / 256, 256>>>();
    count_kernel<<<(NE + 255) / 256, 256>>>(ei);
    scan1_kernel<<<NB_SCAN, 256>>>();
    scan2_kernel<<<1, 256>>>();
    scan3_kernel<<<NB_SCAN, 256>>>();
    fill_kernel<<<(NE + 255) / 256, 256>>>(ei);
    sedge_kernel<<<(NE + 255) / 256, 256>>>(ei, ea);

    for (int l = 0; l < NLAYERS; l++) {
        int first = (l == 0) ? 1 : 0;
        int last  = (l == NLAYERS - 1) ? 1 : 0;

        agg_kernel<<<(NN * 32 + 255) / 256, 256>>>(
            x, first, ew1 + (size_t)l * 128, ew2 + (size_t)l * 3 * 128);

        dim3 ggrid(2, (NN + 127) / 128);
        gemm_tc_kernel<<<ggrid, 256>>>(
            x, first, mlp_w + (size_t)l * 512 * 256, mlp_b + (size_t)l * 256);

        zero_stats_kernel<<<1, 512>>>();
        bnstat_kernel<<<(NN + 127) / 128, 256>>>();
        bnapply_kernel<<<(NN * HID / 4 + 255) / 256, 256>>>(
            out, last, bn_g + (size_t)l * 256, bn_b + (size_t)l * 256, last ? 0 : 1);
    }
}

// round 8
// speedup vs baseline: 1.5563x; 1.5563x over previous
#include <cuda_runtime.h>
#include <cstdint>

#define NN 50000
#define NE 320000
#define HID 256
#define NLAYERS 5
#define BN_EPS 1e-5f
#define NB_SCAN ((NN + 255) / 256)   // 196

// ---------------- scratch (device globals; no allocation allowed) -------------
__device__ float g_h[(size_t)NN * HID];
__device__ float g_agg[(size_t)NN * HID];
__device__ float g_tmp[(size_t)NN * HID];
__device__ float g_dinv[NN];
__device__ int   g_degi[NN];
__device__ int   g_off[NN + 1];
__device__ int   g_cur[NN];
__device__ int   g_row[NE];
__device__ float g_nrm[NE];
__device__ float g_S[(size_t)NN * 4];
__device__ float g_cs[HID];
__device__ float g_cs2[HID];
__device__ int   g_part[256];
__device__ int   g_is64;

// ---------------- edge-index dtype detection ----------------------------------
__global__ void detect_kernel(const int* __restrict__ ei32) {
    __shared__ int nz;
    if (threadIdx.x == 0) nz = 0;
    __syncthreads();
    int cnt = 0;
    for (int i = threadIdx.x; i < 4096; i += blockDim.x)
        if (ei32[2 * i + 1] != 0) cnt++;
    atomicAdd(&nz, cnt);
    __syncthreads();
    if (threadIdx.x == 0) g_is64 = (nz == 0) ? 1 : 0;
}

__device__ __forceinline__ int fetch_idx(const void* ei, int part, int e) {
    int v;
    if (g_is64) v = (int)((const long long*)ei)[(size_t)part * NE + e];
    else        v = ((const int*)ei)[(size_t)part * NE + e];
    return (v < 0 || v >= NN) ? 0 : v;
}

// ---------------- CSR build ---------------------------------------------------
__global__ void zero_init_kernel() {
    int i = blockIdx.x * blockDim.x + threadIdx.x;
    if (i < NN) { g_degi[i] = 0; g_cur[i] = 0; }
    if (i < NN * 4) g_S[i] = 0.0f;
}

__global__ void count_kernel(const void* __restrict__ ei) {
    int e = blockIdx.x * blockDim.x + threadIdx.x;
    if (e < NE) atomicAdd(&g_degi[fetch_idx(ei, 1, e)], 1);
}

__global__ void scan1_kernel() {
    __shared__ int sh[256];
    int i = blockIdx.x * 256 + threadIdx.x;
    int v = (i < NN) ? g_degi[i] : 0;
    sh[threadIdx.x] = v;
    __syncthreads();
    for (int s = 128; s > 0; s >>= 1) {
        if (threadIdx.x < s) sh[threadIdx.x] += sh[threadIdx.x + s];
        __syncthreads();
    }
    if (threadIdx.x == 0) g_part[blockIdx.x] = sh[0];
}

__global__ void scan2_kernel() {
    __shared__ int sh[256];
    int t = threadIdx.x;
    sh[t] = (t < NB_SCAN) ? g_part[t] : 0;
    __syncthreads();
    for (int off = 1; off < 256; off <<= 1) {
        int v = (t >= off) ? sh[t - off] : 0;
        __syncthreads();
        sh[t] += v;
        __syncthreads();
    }
    g_part[t] = (t == 0) ? 0 : sh[t - 1];
}

__global__ void scan3_kernel() {
    __shared__ int sh[256];
    int t = threadIdx.x;
    int i = blockIdx.x * 256 + t;
    int v = (i < NN) ? g_degi[i] : 0;
    sh[t] = v;
    __syncthreads();
    for (int off = 1; off < 256; off <<= 1) {
        int x = (t >= off) ? sh[t - off] : 0;
        __syncthreads();
        sh[t] += x;
        __syncthreads();
    }
    int excl = sh[t] - v + g_part[blockIdx.x];
    if (i < NN) {
        g_off[i] = excl;
        g_dinv[i] = (v > 0) ? rsqrtf((float)v) : 0.0f;
        if (i == NN - 1) g_off[NN] = excl + v;
    }
}

__global__ void fill_kernel(const void* __restrict__ ei) {
    int e = blockIdx.x * blockDim.x + threadIdx.x;
    if (e < NE) {
        int r = fetch_idx(ei, 0, e);
        int c = fetch_idx(ei, 1, e);
        int p = atomicAdd(&g_cur[c], 1);
        int slot = g_off[c] + p;
        if (slot >= 0 && slot < NE) {
            g_row[slot] = r;
            g_nrm[slot] = g_dinv[r] * g_dinv[c];
        }
    }
}

__global__ void sedge_kernel(const void* __restrict__ ei,
                             const float* __restrict__ ea) {
    int e = blockIdx.x * blockDim.x + threadIdx.x;
    if (e < NE) {
        int r = fetch_idx(ei, 0, e);
        int c = fetch_idx(ei, 1, e);
        float nrm = g_dinv[r] * g_dinv[c];
        float4 v = *(const float4*)(ea + (size_t)e * 4);
        float* s = g_S + (size_t)c * 4;
        atomicAdd(s + 0, nrm * v.x);
        atomicAdd(s + 1, nrm * v.y);
        atomicAdd(s + 2, nrm * v.z);
        atomicAdd(s + 3, nrm * v.w);
    }
}

// ---------------- aggregation: one warp per destination node ------------------
__global__ void __launch_bounds__(256) agg_kernel(
    const float* __restrict__ x_ext, int use_ext,
    const float* __restrict__ ew1, const float* __restrict__ ew2)
{
    int warp = (blockIdx.x * blockDim.x + threadIdx.x) >> 5;
    int ln = threadIdx.x & 31;
    if (warp >= NN) return;

    const float* hin = use_ext ? x_ext : g_h;

    float acc[8];
#pragma unroll
    for (int k = 0; k < 8; k++) acc[k] = 0.0f;

    int s = g_off[warp];
    int e_end = g_off[warp + 1];
    for (int i = s; i < e_end; i++) {
        int r = g_row[i];
        float nrm = g_nrm[i];
        const float* hr = hin + (size_t)r * HID;
#pragma unroll
        for (int k = 0; k < 8; k++)
            acc[k] = fmaf(nrm, __ldg(hr + ln + 32 * k), acc[k]);
    }

    float4 S = *(const float4*)(g_S + (size_t)warp * 4);
    float* o = g_agg + (size_t)warp * HID;
#pragma unroll
    for (int k = 0; k < 8; k++) {
        int j = ln + 32 * k;
        float fea;
        if (k < 4) {
            fea = S.w * ew1[j];
        } else {
            int jj = j - 128;
            fea = fmaf(S.x, ew2[jj], fmaf(S.y, ew2[128 + jj], S.z * ew2[256 + jj]));
        }
        o[j] = acc[k] + fea;
    }
}

// ---------------- GEMM with packed f32x2 FMA (FFMA2) --------------------------
// g_tmp = relu([hin, g_agg] @ W + b);  W [512,256] row-major.
// 128x128 tile, 256 threads, per-thread 8(m) x 4(packed n-pairs).

#define FFMA2(c, aa, bb)                                                       \
    asm volatile("fma.rn.f32x2 %0, %1, %2, %0;" : "+l"(c) : "l"(aa), "l"(bb))

__device__ __forceinline__ unsigned long long splat2(float a) {
    unsigned long long r;
    asm("mov.b64 %0, {%1, %1};" : "=l"(r) : "f"(a));
    return r;
}

__global__ void __launch_bounds__(256) gemm_kernel(
    const float* __restrict__ x_ext, int use_ext,
    const float* __restrict__ W, const float* __restrict__ bias)
{
    __shared__ float As[8][128];
    __shared__ __align__(16) float Bs[8][132];   // 528B rows (8B multiple)
    const int M = NN;
    int tid = threadIdx.x;
    int bx = blockIdx.x;           // 0..1 (N tile)
    int by = blockIdx.y;           // M tile
    int tx = tid & 15;
    int ty = tid >> 4;
    int rowBase = by * 128;

    const float* A1 = use_ext ? x_ext : g_h;

    unsigned long long c2[8][4];   // [mi][n-pair]
#pragma unroll
    for (int i = 0; i < 8; i++)
#pragma unroll
        for (int j = 0; j < 4; j++) c2[i][j] = 0ULL;

    int aRow = tid >> 1;           // 0..127
    int aCol = (tid & 1) * 4;      // 0 or 4
    int bRow = tid >> 5;           // 0..7
    int bCol = (tid & 31) * 4;     // 0..124

    for (int phase = 0; phase < 2; ++phase) {
        const float* A = phase ? (const float*)g_agg : A1;
        const float* Wp = W + (size_t)phase * 256 * 256;
        for (int k0 = 0; k0 < 256; k0 += 8) {
            float4 av = make_float4(0.f, 0.f, 0.f, 0.f);
            int ar = rowBase + aRow;
            if (ar < M) av = *(const float4*)(A + (size_t)ar * 256 + k0 + aCol);
            As[aCol + 0][aRow] = av.x;
            As[aCol + 1][aRow] = av.y;
            As[aCol + 2][aRow] = av.z;
            As[aCol + 3][aRow] = av.w;
            float4 bv = *(const float4*)(Wp + (size_t)(k0 + bRow) * 256 + bx * 128 + bCol);
            Bs[bRow][bCol + 0] = bv.x;
            Bs[bRow][bCol + 1] = bv.y;
            Bs[bRow][bCol + 2] = bv.z;
            Bs[bRow][bCol + 3] = bv.w;
            __syncthreads();
#pragma unroll
            for (int k = 0; k < 8; k++) {
                unsigned long long b2[4];
                const unsigned long long* bp =
                    (const unsigned long long*)(&Bs[k][tx * 8]);
#pragma unroll
                for (int j = 0; j < 4; j++) b2[j] = bp[j];
                float a_[8];
#pragma unroll
                for (int i = 0; i < 8; i++) a_[i] = As[k][ty * 8 + i];
#pragma unroll
                for (int i = 0; i < 8; i++) {
                    unsigned long long aa = splat2(a_[i]);
#pragma unroll
                    for (int j = 0; j < 4; j++) FFMA2(c2[i][j], aa, b2[j]);
                }
            }
            __syncthreads();
        }
    }

    // epilogue: unpack + bias + relu -> g_tmp
#pragma unroll
    for (int i = 0; i < 8; i++) {
        int r = rowBase + ty * 8 + i;
        if (r >= M) continue;
#pragma unroll
        for (int j = 0; j < 4; j += 2) {
            int c = bx * 128 + tx * 8 + j * 2;
            float2 p0 = *(float2*)&c2[i][j];
            float2 p1 = *(float2*)&c2[i][j + 1];
            float4 v;
            v.x = fmaxf(p0.x + bias[c + 0], 0.0f);
            v.y = fmaxf(p0.y + bias[c + 1], 0.0f);
            v.z = fmaxf(p1.x + bias[c + 2], 0.0f);
            v.w = fmaxf(p1.y + bias[c + 3], 0.0f);
            *(float4*)(g_tmp + (size_t)r * 256 + c) = v;
        }
    }
}

// ---------------- BatchNorm ---------------------------------------------------
__global__ void zero_stats_kernel() {
    int t = threadIdx.x;
    if (t < HID) g_cs[t] = 0.0f;
    else if (t < 2 * HID) g_cs2[t - HID] = 0.0f;
}

__global__ void __launch_bounds__(256) bnstat_kernel() {
    int c = threadIdx.x;
    int r0 = blockIdx.x * 128;
    int r1 = min(r0 + 128, NN);
    float s = 0.0f, s2 = 0.0f;
    for (int r = r0; r < r1; r++) {
        float v = g_tmp[(size_t)r * HID + c];
        s += v;
        s2 += v * v;
    }
    atomicAdd(&g_cs[c], s);
    atomicAdd(&g_cs2[c], s2);
}

__global__ void __launch_bounds__(256) bnapply_kernel(
    float* __restrict__ out_ext, int use_ext,
    const float* __restrict__ gamma, const float* __restrict__ beta, int dorelu)
{
    int idx = blockIdx.x * blockDim.x + threadIdx.x;
    if (idx >= NN * HID / 4) return;
    float* O = use_ext ? out_ext : g_h;
    int c4 = idx & 63;
    const float invn = 1.0f / (float)NN;
    float4 cs  = ((const float4*)g_cs)[c4];
    float4 cs2 = ((const float4*)g_cs2)[c4];
    float4 gm  = ((const float4*)gamma)[c4];
    float4 bt  = ((const float4*)beta)[c4];
    float4 xv  = ((const float4*)g_tmp)[idx];
    float4 ov;
    {
        float mu = cs.x * invn, var = cs2.x * invn - mu * mu;
        ov.x = (xv.x - mu) * rsqrtf(var + BN_EPS) * gm.x + bt.x;
        mu = cs.y * invn; var = cs2.y * invn - mu * mu;
        ov.y = (xv.y - mu) * rsqrtf(var + BN_EPS) * gm.y + bt.y;
        mu = cs.z * invn; var = cs2.z * invn - mu * mu;
        ov.z = (xv.z - mu) * rsqrtf(var + BN_EPS) * gm.z + bt.z;
        mu = cs.w * invn; var = cs2.w * invn - mu * mu;
        ov.w = (xv.w - mu) * rsqrtf(var + BN_EPS) * gm.w + bt.w;
    }
    if (dorelu) {
        ov.x = fmaxf(ov.x, 0.0f); ov.y = fmaxf(ov.y, 0.0f);
        ov.z = fmaxf(ov.z, 0.0f); ov.w = fmaxf(ov.w, 0.0f);
    }
    ((float4*)O)[idx] = ov;
}

// ---------------- launch ------------------------------------------------------
extern "C" void kernel_launch(void* const* d_in, const int* in_sizes, int n_in,
                              void* d_out, int out_size) {
    const float* x     = (const float*)d_in[0];
    const void*  ei    = d_in[1];
    const float* ea    = (const float*)d_in[2];
    const float* mlp_w = (const float*)d_in[3];
    const float* mlp_b = (const float*)d_in[4];
    const float* ew1   = (const float*)d_in[5];
    const float* ew2   = (const float*)d_in[6];
    const float* bn_g  = (const float*)d_in[7];
    const float* bn_b  = (const float*)d_in[8];
    float* out = (float*)d_out;

    detect_kernel<<<1, 256>>>((const int*)ei);
    zero_init_kernel<<<(NN * 4 + 255) / 256, 256>>>();
    count_kernel<<<(NE + 255) / 256, 256>>>(ei);
    scan1_kernel<<<NB_SCAN, 256>>>();
    scan2_kernel<<<1, 256>>>();
    scan3_kernel<<<NB_SCAN, 256>>>();
    fill_kernel<<<(NE + 255) / 256, 256>>>(ei);
    sedge_kernel<<<(NE + 255) / 256, 256>>>(ei, ea);

    for (int l = 0; l < NLAYERS; l++) {
        int first = (l == 0) ? 1 : 0;
        int last  = (l == NLAYERS - 1) ? 1 : 0;

        agg_kernel<<<(NN * 32 + 255) / 256, 256>>>(
            x, first, ew1 + (size_t)l * 128, ew2 + (size_t)l * 3 * 128);

        dim3 ggrid(2, (NN + 127) / 128);
        gemm_kernel<<<ggrid, 256>>>(
            x, first, mlp_w + (size_t)l * 512 * 256, mlp_b + (size_t)l * 256);

        zero_stats_kernel<<<1, 512>>>();
        bnstat_kernel<<<(NN + 127) / 128, 256>>>();
        bnapply_kernel<<<(NN * HID / 4 + 255) / 256, 256>>>(
            out, last, bn_g + (size_t)l * 256, bn_b + (size_t)l * 256, last ? 0 : 1);
    }
}

// round 9
// speedup vs baseline: 1.7987x; 1.1558x over previous
#include <cuda_runtime.h>
#include <cuda_bf16.h>
#include <cstdint>

#define NN 50000
#define NE 320000
#define HID 256
#define NLAYERS 5
#define BN_EPS 1e-5f
#define NB_SCAN ((NN + 255) / 256)   // 196

// ---------------- scratch (device globals; no allocation allowed) -------------
__device__ float g_h[(size_t)NN * HID];
__device__ float g_agg[(size_t)NN * HID];
__device__ float g_tmp[(size_t)NN * HID];
__device__ float g_dinv[NN];
__device__ int   g_degi[NN];
__device__ int   g_off[NN + 1];
__device__ int   g_cur[NN];
__device__ int   g_row[NE];
__device__ float g_nrm[NE];
__device__ float g_S[(size_t)NN * 4];
__device__ float g_cs[HID];
__device__ float g_cs2[HID];
__device__ int   g_part[256];
__device__ int   g_is64;

// ---------------- edge-index dtype detection ----------------------------------
__global__ void detect_kernel(const int* __restrict__ ei32) {
    __shared__ int nz;
    if (threadIdx.x == 0) nz = 0;
    __syncthreads();
    int cnt = 0;
    for (int i = threadIdx.x; i < 4096; i += blockDim.x)
        if (ei32[2 * i + 1] != 0) cnt++;
    atomicAdd(&nz, cnt);
    __syncthreads();
    if (threadIdx.x == 0) g_is64 = (nz == 0) ? 1 : 0;
}

__device__ __forceinline__ int fetch_idx(const void* ei, int part, int e) {
    int v;
    if (g_is64) v = (int)((const long long*)ei)[(size_t)part * NE + e];
    else        v = ((const int*)ei)[(size_t)part * NE + e];
    return (v < 0 || v >= NN) ? 0 : v;
}

// ---------------- CSR build ---------------------------------------------------
__global__ void zero_init_kernel() {
    int i = blockIdx.x * blockDim.x + threadIdx.x;
    if (i < NN) { g_degi[i] = 0; g_cur[i] = 0; }
    if (i < NN * 4) g_S[i] = 0.0f;
}

__global__ void count_kernel(const void* __restrict__ ei) {
    int e = blockIdx.x * blockDim.x + threadIdx.x;
    if (e < NE) atomicAdd(&g_degi[fetch_idx(ei, 1, e)], 1);
}

__global__ void scan1_kernel() {
    __shared__ int sh[256];
    int i = blockIdx.x * 256 + threadIdx.x;
    int v = (i < NN) ? g_degi[i] : 0;
    sh[threadIdx.x] = v;
    __syncthreads();
    for (int s = 128; s > 0; s >>= 1) {
        if (threadIdx.x < s) sh[threadIdx.x] += sh[threadIdx.x + s];
        __syncthreads();
    }
    if (threadIdx.x == 0) g_part[blockIdx.x] = sh[0];
}

__global__ void scan2_kernel() {
    __shared__ int sh[256];
    int t = threadIdx.x;
    sh[t] = (t < NB_SCAN) ? g_part[t] : 0;
    __syncthreads();
    for (int off = 1; off < 256; off <<= 1) {
        int v = (t >= off) ? sh[t - off] : 0;
        __syncthreads();
        sh[t] += v;
        __syncthreads();
    }
    g_part[t] = (t == 0) ? 0 : sh[t - 1];
}

__global__ void scan3_kernel() {
    __shared__ int sh[256];
    int t = threadIdx.x;
    int i = blockIdx.x * 256 + t;
    int v = (i < NN) ? g_degi[i] : 0;
    sh[t] = v;
    __syncthreads();
    for (int off = 1; off < 256; off <<= 1) {
        int x = (t >= off) ? sh[t - off] : 0;
        __syncthreads();
        sh[t] += x;
        __syncthreads();
    }
    int excl = sh[t] - v + g_part[blockIdx.x];
    if (i < NN) {
        g_off[i] = excl;
        g_dinv[i] = (v > 0) ? rsqrtf((float)v) : 0.0f;
        if (i == NN - 1) g_off[NN] = excl + v;
    }
}

__global__ void fill_kernel(const void* __restrict__ ei) {
    int e = blockIdx.x * blockDim.x + threadIdx.x;
    if (e < NE) {
        int r = fetch_idx(ei, 0, e);
        int c = fetch_idx(ei, 1, e);
        int p = atomicAdd(&g_cur[c], 1);
        int slot = g_off[c] + p;
        if (slot >= 0 && slot < NE) {
            g_row[slot] = r;
            g_nrm[slot] = g_dinv[r] * g_dinv[c];
        }
    }
}

__global__ void sedge_kernel(const void* __restrict__ ei,
                             const float* __restrict__ ea) {
    int e = blockIdx.x * blockDim.x + threadIdx.x;
    if (e < NE) {
        int r = fetch_idx(ei, 0, e);
        int c = fetch_idx(ei, 1, e);
        float nrm = g_dinv[r] * g_dinv[c];
        float4 v = *(const float4*)(ea + (size_t)e * 4);
        float* s = g_S + (size_t)c * 4;
        atomicAdd(s + 0, nrm * v.x);
        atomicAdd(s + 1, nrm * v.y);
        atomicAdd(s + 2, nrm * v.z);
        atomicAdd(s + 3, nrm * v.w);
    }
}

// ---------------- aggregation: one warp per destination node ------------------
__global__ void __launch_bounds__(256) agg_kernel(
    const float* __restrict__ x_ext, int use_ext,
    const float* __restrict__ ew1, const float* __restrict__ ew2)
{
    int warp = (blockIdx.x * blockDim.x + threadIdx.x) >> 5;
    int ln = threadIdx.x & 31;
    if (warp >= NN) return;

    const float* hin = use_ext ? x_ext : g_h;

    float acc[8];
#pragma unroll
    for (int k = 0; k < 8; k++) acc[k] = 0.0f;

    int s = g_off[warp];
    int e_end = g_off[warp + 1];
    for (int i = s; i < e_end; i++) {
        int r = g_row[i];
        float nrm = g_nrm[i];
        const float* hr = hin + (size_t)r * HID;
#pragma unroll
        for (int k = 0; k < 8; k++)
            acc[k] = fmaf(nrm, __ldg(hr + ln + 32 * k), acc[k]);
    }

    float4 S = *(const float4*)(g_S + (size_t)warp * 4);
    float* o = g_agg + (size_t)warp * HID;
#pragma unroll
    for (int k = 0; k < 8; k++) {
        int j = ln + 32 * k;
        float fea;
        if (k < 4) {
            fea = S.w * ew1[j];
        } else {
            int jj = j - 128;
            fea = fmaf(S.x, ew2[jj], fmaf(S.y, ew2[128 + jj], S.z * ew2[256 + jj]));
        }
        o[j] = acc[k] + fea;
    }
}

// ================= bf16x3 tensor-core GEMM (legacy mma.sync + ldmatrix) =======
// g_tmp = relu([hin, g_agg] @ W + b);  W [512,256] row-major.
// 128x128 CTA tile, 8 warps (2m x 4n), warp tile 64x32, k-chunk 32, 2 stages.
// a = aH + aL, b = bH + bL (bf16); acc += aH*bH + aH*bL + aL*bH (fp32).

#define APITCH 80           // bytes per smem row (32 bf16 + 8 pad) — LDSM conflict-free
#define STG    40960        // per-stage bytes: 4 arrays * 128 * 80
#define SMEM_DYN (2 * STG)  // 81920

__device__ __forceinline__ uint32_t smem_u32(const void* p) {
    uint32_t a;
    asm("{ .reg .u64 t; cvta.to.shared.u64 t, %1; cvt.u32.u64 %0, t; }"
        : "=r"(a) : "l"(p));
    return a;
}
__device__ __forceinline__ uint32_t bfpack(float a, float b) {
    __nv_bfloat162 t = __floats2bfloat162_rn(a, b);
    return *reinterpret_cast<uint32_t*>(&t);
}
__device__ __forceinline__ void bfsplit(float v, float& h, float& l) {
    h = __bfloat162float(__float2bfloat16_rn(v));
    l = v - h;
}

#define LDSM4(r0, r1, r2, r3, addr)                                            \
    asm volatile("ldmatrix.sync.aligned.m8n8.x4.shared.b16 {%0,%1,%2,%3}, [%4];" \
                 : "=r"(r0), "=r"(r1), "=r"(r2), "=r"(r3) : "r"(addr))

#define MMA16(d, a, b0, b1)                                                    \
    asm volatile(                                                              \
        "mma.sync.aligned.m16n8k16.row.col.f32.bf16.bf16.f32 "                 \
        "{%0,%1,%2,%3}, {%4,%5,%6,%7}, {%8,%9}, {%0,%1,%2,%3};"                \
        : "+f"(d[0]), "+f"(d[1]), "+f"(d[2]), "+f"(d[3])                       \
        : "r"(a[0]), "r"(a[1]), "r"(a[2]), "r"(a[3]), "r"(b0), "r"(b1))

__global__ void __launch_bounds__(256, 1) gemm_bf16x3(
    const float* __restrict__ x_ext, int use_ext,
    const float* __restrict__ W, const float* __restrict__ bias)
{
    extern __shared__ char dsm[];
    const float* A1 = use_ext ? x_ext : g_h;
    int tid = threadIdx.x;
    int wid = tid >> 5, lane = tid & 31;
    int gid = lane >> 2, tig = lane & 3;
    int warp_m = wid >> 2, warp_n = wid & 3;
    int rowBase = blockIdx.y * 128;
    int colBase = blockIdx.x * 128;
    uint32_t sbase = smem_u32(dsm);

    float acc[4][4][4];
#pragma unroll
    for (int mi = 0; mi < 4; mi++)
#pragma unroll
        for (int ni = 0; ni < 4; ni++)
#pragma unroll
            for (int q = 0; q < 4; q++) acc[mi][ni][q] = 0.0f;

    // per-thread staging coordinates (constant across chunks)
    int aRow0 = tid >> 3;            // 0..31 (+32*i)
    int aK4   = (tid & 7) * 4;       // 0..28
    int bK0   = tid >> 5;            // 0..7 (+8*i)
    int bN4   = (tid & 31) * 4;      // 0..124

    float4 pa[4], pb[4];

    // prologue: load chunk 0 and store to stage 0
#pragma unroll
    for (int i = 0; i < 4; i++) {
        int r = rowBase + aRow0 + 32 * i;
        pa[i] = make_float4(0.f, 0.f, 0.f, 0.f);
        if (r < NN) pa[i] = *(const float4*)(A1 + (size_t)r * 256 + aK4);
        pb[i] = *(const float4*)(W + (size_t)(bK0 + 8 * i) * 256 + colBase + bN4);
    }
    {
        char* aH = dsm;           char* aL = dsm + 10240;
        char* bH = dsm + 20480;   char* bL = dsm + 30720;
#pragma unroll
        for (int i = 0; i < 4; i++) {
            int row = aRow0 + 32 * i;
            float h0, l0, h1, l1, h2, l2, h3, l3;
            bfsplit(pa[i].x, h0, l0); bfsplit(pa[i].y, h1, l1);
            bfsplit(pa[i].z, h2, l2); bfsplit(pa[i].w, h3, l3);
            *(uint2*)(aH + row * APITCH + aK4 * 2) = make_uint2(bfpack(h0, h1), bfpack(h2, h3));
            *(uint2*)(aL + row * APITCH + aK4 * 2) = make_uint2(bfpack(l0, l1), bfpack(l2, l3));
            int k = bK0 + 8 * i;
            float f[4] = {pb[i].x, pb[i].y, pb[i].z, pb[i].w};
#pragma unroll
            for (int q = 0; q < 4; q++) {
                float hh, ll;
                bfsplit(f[q], hh, ll);
                *(__nv_bfloat16*)(bH + (bN4 + q) * APITCH + k * 2) = __float2bfloat16_rn(hh);
                *(__nv_bfloat16*)(bL + (bN4 + q) * APITCH + k * 2) = __float2bfloat16_rn(ll);
            }
        }
    }
    __syncthreads();

    for (int c = 0; c < 16; c++) {
        int p = c & 1;
        // prefetch chunk c+1 to regs (long-latency loads issued before MMA block)
        if (c < 15) {
            int cn = c + 1;
            const float* A = (cn < 8) ? A1 : (const float*)g_agg;
            int ka = (cn & 7) * 32;
            int k0 = cn * 32;
#pragma unroll
            for (int i = 0; i < 4; i++) {
                int r = rowBase + aRow0 + 32 * i;
                pa[i] = make_float4(0.f, 0.f, 0.f, 0.f);
                if (r < NN) pa[i] = *(const float4*)(A + (size_t)r * 256 + ka + aK4);
                pb[i] = *(const float4*)(W + (size_t)(k0 + bK0 + 8 * i) * 256 + colBase + bN4);
            }
        }

        // MMA on stage p
        uint32_t sA = sbase + p * STG;
        uint32_t sAL = sA + 10240;
        uint32_t sB = sA + 20480;
        uint32_t sBL = sA + 30720;
#pragma unroll
        for (int s = 0; s < 2; s++) {
            int kb = s * 16;
            uint32_t aH4[4][4], aL4[4][4], bH2[4][2], bL2[4][2];
            int rla = (lane & 15);
            int kha = (kb + ((lane >> 4) << 3)) * 2;
#pragma unroll
            for (int mi = 0; mi < 4; mi++) {
                uint32_t off = (uint32_t)((warp_m * 64 + mi * 16 + rla) * APITCH) + kha;
                LDSM4(aH4[mi][0], aH4[mi][1], aH4[mi][2], aH4[mi][3], sA + off);
                LDSM4(aL4[mi][0], aL4[mi][1], aL4[mi][2], aL4[mi][3], sAL + off);
            }
            int nlb = (lane & 7) + ((lane >> 4) << 3);
            int klb = (kb + (((lane >> 3) & 1) << 3)) * 2;
#pragma unroll
            for (int j = 0; j < 2; j++) {
                uint32_t off = (uint32_t)((warp_n * 32 + j * 16 + nlb) * APITCH) + klb;
                LDSM4(bH2[2 * j][0], bH2[2 * j][1], bH2[2 * j + 1][0], bH2[2 * j + 1][1], sB + off);
                LDSM4(bL2[2 * j][0], bL2[2 * j][1], bL2[2 * j + 1][0], bL2[2 * j + 1][1], sBL + off);
            }
#pragma unroll
            for (int mi = 0; mi < 4; mi++)
#pragma unroll
                for (int ni = 0; ni < 4; ni++) {
                    MMA16(acc[mi][ni], aH4[mi], bL2[ni][0], bL2[ni][1]);
                    MMA16(acc[mi][ni], aL4[mi], bH2[ni][0], bH2[ni][1]);
                    MMA16(acc[mi][ni], aH4[mi], bH2[ni][0], bH2[ni][1]);
                }
        }

        // store prefetched chunk into the other stage
        if (c < 15) {
            int pn = (c + 1) & 1;
            char* aH = dsm + pn * STG;  char* aL = aH + 10240;
            char* bH = aH + 20480;      char* bL = aH + 30720;
#pragma unroll
            for (int i = 0; i < 4; i++) {
                int row = aRow0 + 32 * i;
                float h0, l0, h1, l1, h2, l2, h3, l3;
                bfsplit(pa[i].x, h0, l0); bfsplit(pa[i].y, h1, l1);
                bfsplit(pa[i].z, h2, l2); bfsplit(pa[i].w, h3, l3);
                *(uint2*)(aH + row * APITCH + aK4 * 2) = make_uint2(bfpack(h0, h1), bfpack(h2, h3));
                *(uint2*)(aL + row * APITCH + aK4 * 2) = make_uint2(bfpack(l0, l1), bfpack(l2, l3));
                int k = bK0 + 8 * i;
                float f[4] = {pb[i].x, pb[i].y, pb[i].z, pb[i].w};
#pragma unroll
                for (int q = 0; q < 4; q++) {
                    float hh, ll;
                    bfsplit(f[q], hh, ll);
                    *(__nv_bfloat16*)(bH + (bN4 + q) * APITCH + k * 2) = __float2bfloat16_rn(hh);
                    *(__nv_bfloat16*)(bL + (bN4 + q) * APITCH + k * 2) = __float2bfloat16_rn(ll);
                }
            }
        }
        __syncthreads();
    }

    // epilogue: bias + relu -> g_tmp
#pragma unroll
    for (int mi = 0; mi < 4; mi++) {
        int r0 = rowBase + warp_m * 64 + mi * 16 + gid;
        int r1 = r0 + 8;
#pragma unroll
        for (int ni = 0; ni < 4; ni++) {
            int col = colBase + warp_n * 32 + ni * 8 + tig * 2;
            float b0 = __ldg(bias + col), b1 = __ldg(bias + col + 1);
            if (r0 < NN) {
                float2 v;
                v.x = fmaxf(acc[mi][ni][0] + b0, 0.0f);
                v.y = fmaxf(acc[mi][ni][1] + b1, 0.0f);
                *(float2*)(g_tmp + (size_t)r0 * 256 + col) = v;
            }
            if (r1 < NN) {
                float2 v;
                v.x = fmaxf(acc[mi][ni][2] + b0, 0.0f);
                v.y = fmaxf(acc[mi][ni][3] + b1, 0.0f);
                *(float2*)(g_tmp + (size_t)r1 * 256 + col) = v;
            }
        }
    }
}

// ---------------- BatchNorm ---------------------------------------------------
__global__ void zero_stats_kernel() {
    int t = threadIdx.x;
    if (t < HID) g_cs[t] = 0.0f;
    else if (t < 2 * HID) g_cs2[t - HID] = 0.0f;
}

__global__ void __launch_bounds__(256) bnstat_kernel() {
    int c = threadIdx.x;
    int r0 = blockIdx.x * 128;
    int r1 = min(r0 + 128, NN);
    float s = 0.0f, s2 = 0.0f;
    for (int r = r0; r < r1; r++) {
        float v = g_tmp[(size_t)r * HID + c];
        s += v;
        s2 += v * v;
    }
    atomicAdd(&g_cs[c], s);
    atomicAdd(&g_cs2[c], s2);
}

__global__ void __launch_bounds__(256) bnapply_kernel(
    float* __restrict__ out_ext, int use_ext,
    const float* __restrict__ gamma, const float* __restrict__ beta, int dorelu)
{
    int idx = blockIdx.x * blockDim.x + threadIdx.x;
    if (idx >= NN * HID / 4) return;
    float* O = use_ext ? out_ext : g_h;
    int c4 = idx & 63;
    const float invn = 1.0f / (float)NN;
    float4 cs  = ((const float4*)g_cs)[c4];
    float4 cs2 = ((const float4*)g_cs2)[c4];
    float4 gm  = ((const float4*)gamma)[c4];
    float4 bt  = ((const float4*)beta)[c4];
    float4 xv  = ((const float4*)g_tmp)[idx];
    float4 ov;
    {
        float mu = cs.x * invn, var = cs2.x * invn - mu * mu;
        ov.x = (xv.x - mu) * rsqrtf(var + BN_EPS) * gm.x + bt.x;
        mu = cs.y * invn; var = cs2.y * invn - mu * mu;
        ov.y = (xv.y - mu) * rsqrtf(var + BN_EPS) * gm.y + bt.y;
        mu = cs.z * invn; var = cs2.z * invn - mu * mu;
        ov.z = (xv.z - mu) * rsqrtf(var + BN_EPS) * gm.z + bt.z;
        mu = cs.w * invn; var = cs2.w * invn - mu * mu;
        ov.w = (xv.w - mu) * rsqrtf(var + BN_EPS) * gm.w + bt.w;
    }
    if (dorelu) {
        ov.x = fmaxf(ov.x, 0.0f); ov.y = fmaxf(ov.y, 0.0f);
        ov.z = fmaxf(ov.z, 0.0f); ov.w = fmaxf(ov.w, 0.0f);
    }
    ((float4*)O)[idx] = ov;
}

// ---------------- launch ------------------------------------------------------
extern "C" void kernel_launch(void* const* d_in, const int* in_sizes, int n_in,
                              void* d_out, int out_size) {
    const float* x     = (const float*)d_in[0];
    const void*  ei    = d_in[1];
    const float* ea    = (const float*)d_in[2];
    const float* mlp_w = (const float*)d_in[3];
    const float* mlp_b = (const float*)d_in[4];
    const float* ew1   = (const float*)d_in[5];
    const float* ew2   = (const float*)d_in[6];
    const float* bn_g  = (const float*)d_in[7];
    const float* bn_b  = (const float*)d_in[8];
    float* out = (float*)d_out;

    cudaFuncSetAttribute(gemm_bf16x3, cudaFuncAttributeMaxDynamicSharedMemorySize,
                         SMEM_DYN);

    detect_kernel<<<1, 256>>>((const int*)ei);
    zero_init_kernel<<<(NN * 4 + 255) / 256, 256>>>();
    count_kernel<<<(NE + 255) / 256, 256>>>(ei);
    scan1_kernel<<<NB_SCAN, 256>>>();
    scan2_kernel<<<1, 256>>>();
    scan3_kernel<<<NB_SCAN, 256>>>();
    fill_kernel<<<(NE + 255) / 256, 256>>>(ei);
    sedge_kernel<<<(NE + 255) / 256, 256>>>(ei, ea);

    for (int l = 0; l < NLAYERS; l++) {
        int first = (l == 0) ? 1 : 0;
        int last  = (l == NLAYERS - 1) ? 1 : 0;

        agg_kernel<<<(NN * 32 + 255) / 256, 256>>>(
            x, first, ew1 + (size_t)l * 128, ew2 + (size_t)l * 3 * 128);

        dim3 ggrid(2, (NN + 127) / 128);
        gemm_bf16x3<<<ggrid, 256, SMEM_DYN>>>(
            x, first, mlp_w + (size_t)l * 512 * 256, mlp_b + (size_t)l * 256);

        zero_stats_kernel<<<1, 512>>>();
        bnstat_kernel<<<(NN + 127) / 128, 256>>>();
        bnapply_kernel<<<(NN * HID / 4 + 255) / 256, 256>>>(
            out, last, bn_g + (size_t)l * 256, bn_b + (size_t)l * 256, last ? 0 : 1);
    }
}

// round 11
// speedup vs baseline: 3.0285x; 1.6837x over previous
#include <cuda_runtime.h>
#include <cuda_bf16.h>
#include <cstdint>

#define NN 50000
#define NE 320000
#define HID 256
#define NLAYERS 5
#define BN_EPS 1e-5f
#define NB_SCAN ((NN + 255) / 256)   // 196

// ---------------- scratch (device globals; no allocation allowed) -------------
__device__ float g_h[(size_t)NN * HID];          // fp32 h (for agg gather)
__device__ float g_tmp[(size_t)NN * HID];        // pre-BN activations
__device__ __nv_bfloat16 g_hh[(size_t)NN * HID]; // h split hi (GEMM A, k<256)
__device__ __nv_bfloat16 g_hl[(size_t)NN * HID]; // h split lo
__device__ __nv_bfloat16 g_gh[(size_t)NN * HID]; // agg split hi (GEMM A, k>=256)
__device__ __nv_bfloat16 g_gl[(size_t)NN * HID]; // agg split lo
__device__ __nv_bfloat16 g_wh[(size_t)NLAYERS * 256 * 512]; // W^T split hi [l][n][k]
__device__ __nv_bfloat16 g_wl[(size_t)NLAYERS * 256 * 512]; // W^T split lo
__device__ float g_dinv[NN];
__device__ int   g_degi[NN];
__device__ int   g_off[NN + 1];
__device__ int   g_cur[NN];
__device__ int   g_row[NE];
__device__ float g_nrm[NE];
__device__ float g_S[(size_t)NN * 4];
__device__ float g_cs[HID];
__device__ float g_cs2[HID];
__device__ int   g_part[256];
__device__ int   g_is64;

// ---------------- helpers ------------------------------------------------------
__device__ __forceinline__ uint32_t smem_u32(const void* p) {
    uint32_t a;
    asm("{ .reg .u64 t; cvta.to.shared.u64 t, %1; cvt.u32.u64 %0, t; }"
        : "=r"(a) : "l"(p));
    return a;
}
__device__ __forceinline__ uint32_t bfpack(float a, float b) {
    __nv_bfloat162 t = __floats2bfloat162_rn(a, b);
    return *reinterpret_cast<uint32_t*>(&t);
}
__device__ __forceinline__ void bfsplit(float v, float& h, float& l) {
    h = __bfloat162float(__float2bfloat16_rn(v));
    l = v - h;
}
__device__ __forceinline__ void cpa16(uint32_t dst, const void* src) {
    asm volatile("cp.async.cg.shared.global [%0], [%1], 16;"
                 :: "r"(dst), "l"(src) : "memory");
}

// ---------------- edge-index dtype detection ----------------------------------
__global__ void detect_kernel(const int* __restrict__ ei32) {
    __shared__ int nz;
    if (threadIdx.x == 0) nz = 0;
    __syncthreads();
    int cnt = 0;
    for (int i = threadIdx.x; i < 4096; i += blockDim.x)
        if (ei32[2 * i + 1] != 0) cnt++;
    atomicAdd(&nz, cnt);
    __syncthreads();
    if (threadIdx.x == 0) g_is64 = (nz == 0) ? 1 : 0;
}

__device__ __forceinline__ int fetch_idx(const void* ei, int part, int e) {
    int v;
    if (g_is64) v = (int)((const long long*)ei)[(size_t)part * NE + e];
    else        v = ((const int*)ei)[(size_t)part * NE + e];
    return (v < 0 || v >= NN) ? 0 : v;
}

// ---------------- CSR build ---------------------------------------------------
__global__ void zero_init_kernel() {
    int i = blockIdx.x * blockDim.x + threadIdx.x;
    if (i < NN) { g_degi[i] = 0; g_cur[i] = 0; }
    if (i < NN * 4) g_S[i] = 0.0f;
}

__global__ void count_kernel(const void* __restrict__ ei) {
    int e = blockIdx.x * blockDim.x + threadIdx.x;
    if (e < NE) atomicAdd(&g_degi[fetch_idx(ei, 1, e)], 1);
}

__global__ void scan1_kernel() {
    __shared__ int sh[256];
    int i = blockIdx.x * 256 + threadIdx.x;
    int v = (i < NN) ? g_degi[i] : 0;
    sh[threadIdx.x] = v;
    __syncthreads();
    for (int s = 128; s > 0; s >>= 1) {
        if (threadIdx.x < s) sh[threadIdx.x] += sh[threadIdx.x + s];
        __syncthreads();
    }
    if (threadIdx.x == 0) g_part[blockIdx.x] = sh[0];
}

__global__ void scan2_kernel() {
    __shared__ int sh[256];
    int t = threadIdx.x;
    sh[t] = (t < NB_SCAN) ? g_part[t] : 0;
    __syncthreads();
    for (int off = 1; off < 256; off <<= 1) {
        int v = (t >= off) ? sh[t - off] : 0;
        __syncthreads();
        sh[t] += v;
        __syncthreads();
    }
    g_part[t] = (t == 0) ? 0 : sh[t - 1];
}

__global__ void scan3_kernel() {
    __shared__ int sh[256];
    int t = threadIdx.x;
    int i = blockIdx.x * 256 + t;
    int v = (i < NN) ? g_degi[i] : 0;
    sh[t] = v;
    __syncthreads();
    for (int off = 1; off < 256; off <<= 1) {
        int x = (t >= off) ? sh[t - off] : 0;
        __syncthreads();
        sh[t] += x;
        __syncthreads();
    }
    int excl = sh[t] - v + g_part[blockIdx.x];
    if (i < NN) {
        g_off[i] = excl;
        g_dinv[i] = (v > 0) ? rsqrtf((float)v) : 0.0f;
        if (i == NN - 1) g_off[NN] = excl + v;
    }
}

__global__ void fill_kernel(const void* __restrict__ ei) {
    int e = blockIdx.x * blockDim.x + threadIdx.x;
    if (e < NE) {
        int r = fetch_idx(ei, 0, e);
        int c = fetch_idx(ei, 1, e);
        int p = atomicAdd(&g_cur[c], 1);
        int slot = g_off[c] + p;
        if (slot >= 0 && slot < NE) {
            g_row[slot] = r;
            g_nrm[slot] = g_dinv[r] * g_dinv[c];
        }
    }
}

__global__ void sedge_kernel(const void* __restrict__ ei,
                             const float* __restrict__ ea) {
    int e = blockIdx.x * blockDim.x + threadIdx.x;
    if (e < NE) {
        int r = fetch_idx(ei, 0, e);
        int c = fetch_idx(ei, 1, e);
        float nrm = g_dinv[r] * g_dinv[c];
        float4 v = *(const float4*)(ea + (size_t)e * 4);
        float* s = g_S + (size_t)c * 4;
        atomicAdd(s + 0, nrm * v.x);
        atomicAdd(s + 1, nrm * v.y);
        atomicAdd(s + 2, nrm * v.z);
        atomicAdd(s + 3, nrm * v.w);
    }
}

// ---------------- one-time split kernels ---------------------------------------
__global__ void wsplit_kernel(const float* __restrict__ mlp_w) {
    int idx = blockIdx.x * blockDim.x + threadIdx.x;
    if (idx >= NLAYERS * 512 * 256) return;
    int n = idx & 255;
    int k = (idx >> 8) & 511;
    int l = idx >> 17;
    float h, lo;
    bfsplit(mlp_w[idx], h, lo);
    size_t o = ((size_t)l * 256 + n) * 512 + k;
    g_wh[o] = __float2bfloat16_rn(h);
    g_wl[o] = __float2bfloat16_rn(lo);
}

__global__ void xsplit_kernel(const float* __restrict__ x) {
    int idx = blockIdx.x * blockDim.x + threadIdx.x;
    if (idx >= NN * HID / 4) return;
    float4 v = ((const float4*)x)[idx];
    float h0, l0, h1, l1, h2, l2, h3, l3;
    bfsplit(v.x, h0, l0); bfsplit(v.y, h1, l1);
    bfsplit(v.z, h2, l2); bfsplit(v.w, h3, l3);
    ((uint2*)g_hh)[idx] = make_uint2(bfpack(h0, h1), bfpack(h2, h3));
    ((uint2*)g_hl)[idx] = make_uint2(bfpack(l0, l1), bfpack(l2, l3));
}

// ---------------- aggregation: warp/node, lane = 8 consecutive cols ------------
__global__ void __launch_bounds__(256) agg_kernel(
    const float* __restrict__ x_ext, int use_ext,
    const float* __restrict__ ew1, const float* __restrict__ ew2)
{
    int node = (blockIdx.x * blockDim.x + threadIdx.x) >> 5;
    int ln = threadIdx.x & 31;
    if (node >= NN) return;

    const float* hin = use_ext ? x_ext : g_h;

    float acc[8];
#pragma unroll
    for (int q = 0; q < 8; q++) acc[q] = 0.0f;

    int s = g_off[node];
    int e_end = g_off[node + 1];
    for (int i = s; i < e_end; i++) {
        int r = g_row[i];
        float nrm = g_nrm[i];
        const float* hr = hin + (size_t)r * HID + ln * 8;
        float4 v0 = __ldg((const float4*)hr);
        float4 v1 = __ldg((const float4*)(hr + 4));
        acc[0] = fmaf(nrm, v0.x, acc[0]);
        acc[1] = fmaf(nrm, v0.y, acc[1]);
        acc[2] = fmaf(nrm, v0.z, acc[2]);
        acc[3] = fmaf(nrm, v0.w, acc[3]);
        acc[4] = fmaf(nrm, v1.x, acc[4]);
        acc[5] = fmaf(nrm, v1.y, acc[5]);
        acc[6] = fmaf(nrm, v1.z, acc[6]);
        acc[7] = fmaf(nrm, v1.w, acc[7]);
    }

    float4 S = *(const float4*)(g_S + (size_t)node * 4);
    float hi[8], lo[8];
#pragma unroll
    for (int q = 0; q < 8; q++) {
        int j = ln * 8 + q;
        float fea;
        if (j < 128) {
            fea = S.w * ew1[j];
        } else {
            int jj = j - 128;
            fea = fmaf(S.x, ew2[jj], fmaf(S.y, ew2[128 + jj], S.z * ew2[256 + jj]));
        }
        bfsplit(acc[q] + fea, hi[q], lo[q]);
    }
    uint4 ph = make_uint4(bfpack(hi[0], hi[1]), bfpack(hi[2], hi[3]),
                          bfpack(hi[4], hi[5]), bfpack(hi[6], hi[7]));
    uint4 pl = make_uint4(bfpack(lo[0], lo[1]), bfpack(lo[2], lo[3]),
                          bfpack(lo[4], lo[5]), bfpack(lo[6], lo[7]));
    ((uint4*)g_gh)[node * 32 + ln] = ph;
    ((uint4*)g_gl)[node * 32 + ln] = pl;
}

// ================= bf16x3 tensor-core GEMM (cp.async + ldmatrix) ===============
// g_tmp = relu([h, agg] @ W + b) using pre-split bf16 operands.
// 128x128 CTA tile, 8 warps (2m x 4n), k-chunk 32, 2-stage cp.async pipeline.

#define APITCH 80
#define STG    40960
#define SMEM_DYN (2 * STG)   // 81920

#define LDSM4(r0, r1, r2, r3, addr)                                            \
    asm volatile("ldmatrix.sync.aligned.m8n8.x4.shared.b16 {%0,%1,%2,%3}, [%4];" \
                 : "=r"(r0), "=r"(r1), "=r"(r2), "=r"(r3) : "r"(addr))

#define MMA16(d, a, b0, b1)                                                    \
    asm volatile(                                                              \
        "mma.sync.aligned.m16n8k16.row.col.f32.bf16.bf16.f32 "                 \
        "{%0,%1,%2,%3}, {%4,%5,%6,%7}, {%8,%9}, {%0,%1,%2,%3};"                \
        : "+f"(d[0]), "+f"(d[1]), "+f"(d[2]), "+f"(d[3])                       \
        : "r"(a[0]), "r"(a[1]), "r"(a[2]), "r"(a[3]), "r"(b0), "r"(b1))

__device__ __forceinline__ void stage_chunk(
    uint32_t base, int c, int rowBase, int colBase,
    const __nv_bfloat16* __restrict__ Wh, const __nv_bfloat16* __restrict__ Wl,
    int tid)
{
    const __nv_bfloat16* Ah = (c < 8) ? g_hh : g_gh;
    const __nv_bfloat16* Al = (c < 8) ? g_hl : g_gl;
    int ka = (c & 7) * 32;
    int k0 = c * 32;
#pragma unroll
    for (int t = 0; t < 2; t++) {
        int idx = tid + t * 256;
        int row = idx >> 2, seg = idx & 3;
        int gr = rowBase + row;
        if (gr >= NN) gr = NN - 1;
        uint32_t so = (uint32_t)(row * APITCH + seg * 16);
        const size_t ao = (size_t)gr * 256 + ka + seg * 8;
        cpa16(base + so,         Ah + ao);
        cpa16(base + 10240 + so, Al + ao);
        const size_t bo = (size_t)(colBase + row) * 512 + k0 + seg * 8;
        cpa16(base + 20480 + so, Wh + bo);
        cpa16(base + 30720 + so, Wl + bo);
    }
}

__global__ void __launch_bounds__(256, 2) gemm_bf(
    int layer, const float* __restrict__ mlp_b)
{
    extern __shared__ char dsm[];
    const __nv_bfloat16* Wh = g_wh + (size_t)layer * 256 * 512;
    const __nv_bfloat16* Wl = g_wl + (size_t)layer * 256 * 512;
    const float* bias = mlp_b + (size_t)layer * 256;

    int tid = threadIdx.x;
    int wid = tid >> 5, lane = tid & 31;
    int gid = lane >> 2, tig = lane & 3;
    int warp_m = wid >> 2, warp_n = wid & 3;
    int rowBase = blockIdx.y * 128;
    int colBase = blockIdx.x * 128;
    uint32_t sbase = smem_u32(dsm);

    float acc[4][4][4];
#pragma unroll
    for (int mi = 0; mi < 4; mi++)
#pragma unroll
        for (int ni = 0; ni < 4; ni++)
#pragma unroll
            for (int q = 0; q < 4; q++) acc[mi][ni][q] = 0.0f;

    stage_chunk(sbase, 0, rowBase, colBase, Wh, Wl, tid);
    asm volatile("cp.async.commit_group;");

    for (int c = 0; c < 16; c++) {
        int p = c & 1;
        if (c < 15) {
            stage_chunk(sbase + (1 - p) * STG, c + 1, rowBase, colBase, Wh, Wl, tid);
            asm volatile("cp.async.commit_group;");
            asm volatile("cp.async.wait_group 1;");
        } else {
            asm volatile("cp.async.wait_group 0;");
        }
        __syncthreads();

        uint32_t sA  = sbase + p * STG;
        uint32_t sAL = sA + 10240;
        uint32_t sB  = sA + 20480;
        uint32_t sBL = sA + 30720;
#pragma unroll
        for (int s = 0; s < 2; s++) {
            int kb = s * 16;
            uint32_t aH4[4][4], aL4[4][4], bH2[4][2], bL2[4][2];
            int rla = (lane & 15);
            int kha = (kb + ((lane >> 4) << 3)) * 2;
#pragma unroll
            for (int mi = 0; mi < 4; mi++) {
                uint32_t off = (uint32_t)((warp_m * 64 + mi * 16 + rla) * APITCH) + kha;
                LDSM4(aH4[mi][0], aH4[mi][1], aH4[mi][2], aH4[mi][3], sA + off);
                LDSM4(aL4[mi][0], aL4[mi][1], aL4[mi][2], aL4[mi][3], sAL + off);
            }
            int nlb = (lane & 7) + ((lane >> 4) << 3);
            int klb = (kb + (((lane >> 3) & 1) << 3)) * 2;
#pragma unroll
            for (int j = 0; j < 2; j++) {
                uint32_t off = (uint32_t)((warp_n * 32 + j * 16 + nlb) * APITCH) + klb;
                LDSM4(bH2[2 * j][0], bH2[2 * j][1], bH2[2 * j + 1][0], bH2[2 * j + 1][1], sB + off);
                LDSM4(bL2[2 * j][0], bL2[2 * j][1], bL2[2 * j + 1][0], bL2[2 * j + 1][1], sBL + off);
            }
#pragma unroll
            for (int mi = 0; mi < 4; mi++)
#pragma unroll
                for (int ni = 0; ni < 4; ni++) {
                    MMA16(acc[mi][ni], aH4[mi], bL2[ni][0], bL2[ni][1]);
                    MMA16(acc[mi][ni], aL4[mi], bH2[ni][0], bH2[ni][1]);
                    MMA16(acc[mi][ni], aH4[mi], bH2[ni][0], bH2[ni][1]);
                }
        }
        __syncthreads();
    }

    // epilogue: bias + relu -> g_tmp
#pragma unroll
    for (int mi = 0; mi < 4; mi++) {
        int r0 = rowBase + warp_m * 64 + mi * 16 + gid;
        int r1 = r0 + 8;
#pragma unroll
        for (int ni = 0; ni < 4; ni++) {
            int col = colBase + warp_n * 32 + ni * 8 + tig * 2;
            float b0 = __ldg(bias + col), b1 = __ldg(bias + col + 1);
            if (r0 < NN) {
                float2 v;
                v.x = fmaxf(acc[mi][ni][0] + b0, 0.0f);
                v.y = fmaxf(acc[mi][ni][1] + b1, 0.0f);
                *(float2*)(g_tmp + (size_t)r0 * 256 + col) = v;
            }
            if (r1 < NN) {
                float2 v;
                v.x = fmaxf(acc[mi][ni][2] + b0, 0.0f);
                v.y = fmaxf(acc[mi][ni][3] + b1, 0.0f);
                *(float2*)(g_tmp + (size_t)r1 * 256 + col) = v;
            }
        }
    }
}

// ---------------- BatchNorm ---------------------------------------------------
__global__ void zero_stats_kernel() {
    int t = threadIdx.x;
    if (t < HID) g_cs[t] = 0.0f;
    else if (t < 2 * HID) g_cs2[t - HID] = 0.0f;
}

__global__ void __launch_bounds__(256) bnstat_kernel() {
    int c = threadIdx.x;
    int r0 = blockIdx.x * 128;
    int r1 = min(r0 + 128, NN);
    float s = 0.0f, s2 = 0.0f;
    for (int r = r0; r < r1; r++) {
        float v = g_tmp[(size_t)r * HID + c];
        s += v;
        s2 += v * v;
    }
    atomicAdd(&g_cs[c], s);
    atomicAdd(&g_cs2[c], s2);
}

__global__ void __launch_bounds__(256) bnapply_kernel(
    float* __restrict__ out_ext, int use_ext,
    const float* __restrict__ gamma, const float* __restrict__ beta, int dorelu)
{
    int idx = blockIdx.x * blockDim.x + threadIdx.x;
    if (idx >= NN * HID / 4) return;
    float* O = use_ext ? out_ext : g_h;
    int c4 = idx & 63;
    const float invn = 1.0f / (float)NN;
    float4 cs  = ((const float4*)g_cs)[c4];
    float4 cs2 = ((const float4*)g_cs2)[c4];
    float4 gm  = ((const float4*)gamma)[c4];
    float4 bt  = ((const float4*)beta)[c4];
    float4 xv  = ((const float4*)g_tmp)[idx];
    float4 ov;
    {
        float mu = cs.x * invn, var = cs2.x * invn - mu * mu;
        ov.x = (xv.x - mu) * rsqrtf(var + BN_EPS) * gm.x + bt.x;
        mu = cs.y * invn; var = cs2.y * invn - mu * mu;
        ov.y = (xv.y - mu) * rsqrtf(var + BN_EPS) * gm.y + bt.y;
        mu = cs.z * invn; var = cs2.z * invn - mu * mu;
        ov.z = (xv.z - mu) * rsqrtf(var + BN_EPS) * gm.z + bt.z;
        mu = cs.w * invn; var = cs2.w * invn - mu * mu;
        ov.w = (xv.w - mu) * rsqrtf(var + BN_EPS) * gm.w + bt.w;
    }
    if (dorelu) {
        ov.x = fmaxf(ov.x, 0.0f); ov.y = fmaxf(ov.y, 0.0f);
        ov.z = fmaxf(ov.z, 0.0f); ov.w = fmaxf(ov.w, 0.0f);
    }
    ((float4*)O)[idx] = ov;
    if (!use_ext) {  // feed next layer's GEMM: bf16 hi/lo splits
        float h0, l0, h1, l1, h2, l2, h3, l3;
        bfsplit(ov.x, h0, l0); bfsplit(ov.y, h1, l1);
        bfsplit(ov.z, h2, l2); bfsplit(ov.w, h3, l3);
        ((uint2*)g_hh)[idx] = make_uint2(bfpack(h0, h1), bfpack(h2, h3));
        ((uint2*)g_hl)[idx] = make_uint2(bfpack(l0, l1), bfpack(l2, l3));
    }
}

// ---------------- launch ------------------------------------------------------
extern "C" void kernel_launch(void* const* d_in, const int* in_sizes, int n_in,
                              void* d_out, int out_size) {
    const float* x     = (const float*)d_in[0];
    const void*  ei    = d_in[1];
    const float* ea    = (const float*)d_in[2];
    const float* mlp_w = (const float*)d_in[3];
    const float* mlp_b = (const float*)d_in[4];
    const float* ew1   = (const float*)d_in[5];
    const float* ew2   = (const float*)d_in[6];
    const float* bn_g  = (const float*)d_in[7];
    const float* bn_b  = (const float*)d_in[8];
    float* out = (float*)d_out;

    cudaFuncSetAttribute(gemm_bf, cudaFuncAttributeMaxDynamicSharedMemorySize,
                         SMEM_DYN);

    detect_kernel<<<1, 256>>>((const int*)ei);
    zero_init_kernel<<<(NN * 4 + 255) / 256, 256>>>();
    count_kernel<<<(NE + 255) / 256, 256>>>(ei);
    scan1_kernel<<<NB_SCAN, 256>>>();
    scan2_kernel<<<1, 256>>>();
    scan3_kernel<<<NB_SCAN, 256>>>();
    fill_kernel<<<(NE + 255) / 256, 256>>>(ei);
    sedge_kernel<<<(NE + 255) / 256, 256>>>(ei, ea);
    wsplit_kernel<<<(NLAYERS * 512 * 256 + 255) / 256, 256>>>(mlp_w);
    xsplit_kernel<<<(NN * HID / 4 + 255) / 256, 256>>>(x);

    for (int l = 0; l < NLAYERS; l++) {
        int first = (l == 0) ? 1 : 0;
        int last  = (l == NLAYERS - 1) ? 1 : 0;

        agg_kernel<<<(NN * 32 + 255) / 256, 256>>>(
            x, first, ew1 + (size_t)l * 128, ew2 + (size_t)l * 3 * 128);

        dim3 ggrid(2, (NN + 127) / 128);
        gemm_bf<<<ggrid, 256, SMEM_DYN>>>(l, mlp_b);

        zero_stats_kernel<<<1, 512>>>();
        bnstat_kernel<<<(NN + 127) / 128, 256>>>();
        bnapply_kernel<<<(NN * HID / 4 + 255) / 256, 256>>>(
            out, last, bn_g + (size_t)l * 256, bn_b + (size_t)l * 256, last ? 0 : 1);
    }
}